// round 11
// baseline (speedup 1.0000x reference)
#include <cuda_runtime.h>

// ActiveParticles step, N=4096 — spatial binning + ONE fused persistent kernel.
// Inputs: positions[N,2] f32, orientations[N,2] f32, Deltas[1] f32,
//         rot_noise[N] f32, trans_noise[N,2] f32.
// Output: [5, N, 2] f32 = {new_p, new_u, orientation_sums, leftturns, rightturns}.

#define NMAX  4096
#define GDIM  64
#define CELLS (GDIM * GDIM)
#define NB    128      // blocks: <= 148 SMs -> co-residency unconditional
#define TPB   256

// Grid geometry: span [-2.24e-3, 2.24e-3], cell 7e-5 >= ROC (2.815e-5).
// Clamped cell mapping is monotone & non-expanding: any pair within ROC lands in
// adjacent cells, outliers included. Collision moves (~1e-5) << cell size, so the
// one-time binning stays valid for all 3 collision sweeps (radius 6.3e-6).
#define XMIN  (-2.24e-3f)
#define INVCS (14285.714285714286f)   // 1 / 7e-5

static __device__ float4   g_pu[NMAX];        // orig order (p.x,p.y,u.x,u.y)
static __device__ int      g_ci[NMAX];        // cell id per orig particle
static __device__ unsigned g_cnt[CELLS];      // ZERO-INVARIANT between runs
static __device__ unsigned g_start[CELLS + 1];
static __device__ unsigned g_cur[CELLS];
static __device__ float4   g_spu[NMAX];       // sorted (p,u)
static __device__ int      g_sorig[NMAX];     // sorted -> orig index
static __device__ int      g_scell[NMAX];     // sorted -> cell id
static __device__ float2   g_sposA[NMAX];     // sorted positions ping
static __device__ float2   g_sposB[NMAX];     // sorted positions pong
static __device__ volatile unsigned g_gen;    // barrier generation
static __device__ unsigned g_count;           // barrier arrivals

__device__ __forceinline__ float wsum(float v) {
#pragma unroll
    for (int o = 16; o; o >>= 1) v += __shfl_xor_sync(0xffffffffu, v, o);
    return v;
}

__device__ __forceinline__ unsigned uwscan(unsigned v, int lane) {  // inclusive
#pragma unroll
    for (int o = 1; o < 32; o <<= 1) {
        unsigned t = __shfl_up_sync(0xffffffffu, v, o);
        if (lane >= o) v += t;
    }
    return v;
}

__device__ __forceinline__ float anglewrap(float diff) {
    const float PI_F = 3.1415927410125732f;
    if (diff <= -PI_F) diff = diff - PI_F * floorf(diff / PI_F);  // jnp.mod(diff, PI)
    if (diff >= PI_F) diff -= 2.0f * PI_F;
    return diff;
}

__device__ __forceinline__ float anglediff(float ax, float ay, float bx, float by) {
    return anglewrap(atan2f(ay, ax) - atan2f(by, bx));
}

__device__ __forceinline__ int cell_of(float x, float y) {
    int cx = __float2int_rd((x - XMIN) * INVCS);
    int cy = __float2int_rd((y - XMIN) * INVCS);
    cx = max(0, min(GDIM - 1, cx));
    cy = max(0, min(GDIM - 1, cy));
    return cy * GDIM + cx;
}

// Grid barrier: 128 blocks <= 148 SMs, always co-resident. __threadfence is
// gpu-scope (CCTL.IVALL) -> post-barrier loads see other SMs' writes via L2.
__device__ __forceinline__ void grid_sync() {
    __syncthreads();
    if (threadIdx.x == 0) {
        unsigned my = g_gen;                 // read BEFORE arriving
        __threadfence();
        if (atomicAdd(&g_count, 1u) == NB - 1u) {
            g_count = 0u;
            __threadfence();
            g_gen = my + 1u;
        } else {
            while (g_gen == my) __nanosleep(32);
        }
        __threadfence();
    }
    __syncthreads();
}

// One collision step for sorted slot s; result valid in all lanes.
__device__ __forceinline__ float2 collide_one(const float2* __restrict__ src,
                                              int s, int lane) {
    const float2 pi = src[s];
    const int c = g_scell[s];
    const int cx = c & (GDIM - 1), cy = c >> 6;
    const float TH2 = (float)(2.0 * 3.15e-6) * (float)(2.0 * 3.15e-6);
    const float C21 = (float)(2.1 * 3.15e-6);
    const unsigned uTH2 = __float_as_uint(TH2);

    float mvx = 0.f, mvy = 0.f;
    const int cx0 = max(cx - 1, 0), cx1 = min(cx + 1, GDIM - 1);
#pragma unroll
    for (int dy = -1; dy <= 1; dy++) {
        int ry = cy + dy;
        if ((unsigned)ry < (unsigned)GDIM) {
            int a = (int)g_start[ry * GDIM + cx0];
            int b = (int)g_start[ry * GDIM + cx1 + 1];
            for (int idx = a + lane; idx < b; idx += 32) {
                float2 pj = src[idx];
                float dx = pj.x - pi.x, dyv = pj.y - pi.y;
                float d2 = fmaf(dx, dx, dyv * dyv);
                if ((__float_as_uint(d2) - 1u) < uTH2) {   // 0 < d2 <= TH2
                    float ab = sqrtf(d2);
                    float sc = (C21 - ab) * 0.5f / ab;
                    mvx += dx * sc; mvy += dyv * sc;
                }
            }
        }
    }
    mvx = wsum(mvx); mvy = wsum(mvy);
    return make_float2(pi.x - mvx, pi.y - mvy);
}

__global__ void __launch_bounds__(TPB) fused_kernel(
        const float2* __restrict__ pos, const float2* __restrict__ ori,
        const float* __restrict__ deltas, const float* __restrict__ rnoise,
        const float2* __restrict__ tn, float* __restrict__ out, int n) {
    const int tid  = threadIdx.x;
    const int bid  = blockIdx.x;
    const int lane = tid & 31;
    const int w    = tid >> 5;
    const int gtid = bid * TPB + tid;
    const int gw   = bid * (TPB / 32) + w;       // global warp id, 0..1023
    const int W    = NB * (TPB / 32);            // 1024 warps

    __shared__ float2   s_red[TPB / 32];
    __shared__ unsigned s_wt[TPB / 32];
    __shared__ float2   s_cms;

    // ---- P0: pack + count (g_cnt is zero by invariant) ---------------------------
    if (gtid < n) {
        float2 pp = pos[gtid], uu = ori[gtid];
        g_pu[gtid] = make_float4(pp.x, pp.y, uu.x, uu.y);
        int c = cell_of(pp.x, pp.y);
        g_ci[gtid] = c;
        atomicAdd(&g_cnt[c], 1u);
    }
    grid_sync();

    // ---- P1: every block computes mean(p) redundantly (deterministic order) -----
    {
        float mx = 0.f, my = 0.f;
        for (int i = tid; i < n; i += TPB) { float4 v = g_pu[i]; mx += v.x; my += v.y; }
        mx = wsum(mx); my = wsum(my);
        if (lane == 0) s_red[w] = make_float2(mx, my);
        __syncthreads();
        if (tid == 0) {
            float ax = 0.f, ay = 0.f;
#pragma unroll
            for (int k = 0; k < TPB / 32; k++) { ax += s_red[k].x; ay += s_red[k].y; }
            float invn = 1.0f / fmaxf((float)n, 1.0f);  // max(n_a,1), n_a=n (mask_ra all-true)
            s_cms = make_float2(ax * invn, ay * invn);
        }
        __syncthreads();
    }

    // ---- P2: block 0 scans counts -> g_start/g_cur -------------------------------
    if (bid == 0) {
        unsigned cc[16], s = 0;
#pragma unroll
        for (int k = 0; k < 16; k++) { cc[k] = g_cnt[16 * tid + k]; s += cc[k]; }
        unsigned inc = uwscan(s, lane);
        if (lane == 31) s_wt[w] = inc;
        __syncthreads();
        if (w == 0) {
            unsigned v = (lane < TPB / 32) ? s_wt[lane] : 0u;
            v = uwscan(v, lane);
            if (lane < TPB / 32) s_wt[lane] = v;
        }
        __syncthreads();
        unsigned base = (w ? s_wt[w - 1] : 0u) + inc - s;
#pragma unroll
        for (int k = 0; k < 16; k++) {
            g_start[16 * tid + k] = base;
            g_cur[16 * tid + k] = base;
            base += cc[k];
        }
        if (tid == 0) g_start[CELLS] = (unsigned)n;
    }
    grid_sync();

    // ---- P3: scatter (+ restore g_cnt zero-invariant) ----------------------------
    if (gtid < n) {
        int c = g_ci[gtid];
        unsigned slot = atomicAdd(&g_cur[c], 1u);
        g_spu[slot] = g_pu[gtid];
        g_sorig[slot] = gtid;
        g_scell[slot] = c;
    }
    if (gtid < CELLS) g_cnt[gtid] = 0u;
    grid_sync();

    // ---- P4: per-cell insertion sort by orig index (determinism) -----------------
    if (gtid < CELLS) {
        int a = (int)g_start[gtid], b = (int)g_start[gtid + 1];
        for (int i = a + 1; i < b; i++) {
            float4 key = g_spu[i];
            int ko = g_sorig[i];
            int j = i - 1;
            while (j >= a && g_sorig[j] > ko) {
                g_spu[j + 1] = g_spu[j];
                g_sorig[j + 1] = g_sorig[j];
                j--;
            }
            g_spu[j + 1] = key;
            g_sorig[j + 1] = ko;
        }
    }
    grid_sync();

    // ---- P5: main pass, warp-per-particle (strided) ------------------------------
    for (int s = gw; s < n; s += W) {
        const float4 me = g_spu[s];
        const float pix = me.x, piy = me.y, uix = me.z, uiy = me.w;
        const int c = g_scell[s];
        const int cx = c & (GDIM - 1), cy = c >> 6;

        const float RR2  = (float)(8e-6 * 8e-6);
        const float ROCf = (float)(2.5e-5 + 3.15e-6);
        const float ROC2 = ROCf * ROCf;
        const unsigned uRR2 = __float_as_uint(RR2);

        float nr = 0.f, srx = 0.f, sry = 0.f, osx = 0.f, osy = 0.f;
        const int cx0 = max(cx - 1, 0), cx1 = min(cx + 1, GDIM - 1);
#pragma unroll
        for (int dy = -1; dy <= 1; dy++) {
            int ry = cy + dy;
            if ((unsigned)ry < (unsigned)GDIM) {
                int a = (int)g_start[ry * GDIM + cx0];
                int b = (int)g_start[ry * GDIM + cx1 + 1];
                for (int idx = a + lane; idx < b; idx += 32) {
                    float4 aj = g_spu[idx];
                    float dx = aj.x - pix, dyv = aj.y - piy;
                    float d2 = fmaf(dx, dx, dyv * dyv);
                    if (d2 <= ROC2) {                    // mask_ro (includes self)
                        osx += aj.z; osy += aj.w;
                        if ((__float_as_uint(d2) - 1u) < uRR2) {  // 0 < d2 <= RR2
                            // in_front: wrap(angle(dir)-angle(u_j)) < pi/2
                            //   <=> !(dot<=0 && cross>=0)
                            float cc2 = dx * aj.z + dyv * aj.w;
                            float ss2 = aj.z * dyv - aj.w * dx;
                            if (!(cc2 <= 0.0f && ss2 >= 0.0f)) { nr += 1.f; srx += aj.x; sry += aj.y; }
                        }
                    }
                }
            }
        }
        nr = wsum(nr); srx = wsum(srx); sry = wsum(sry); osx = wsum(osx); osy = wsum(osy);

        // epilogue (all lanes redundant, lane 0 writes)
        float sgn = (nr > 0.f) ? 1.0f : 0.0f;
        float invr = 1.0f / fmaxf(nr, 1.0f);
        float dax = -(srx * invr - pix * sgn);
        float day = -(sry * invr - piy * sgn);

        float Psx = s_cms.x - pix;                       // sign(n_a) == 1
        float Psy = s_cms.y - piy;

        float Delta = __ldg(&deltas[0]);
        float cd = cosf(Delta), sd = sinf(Delta);
        float lx = Psx * cd - Psy * sd, ly = Psx * sd + Psy * cd;  // Ps*e^{+iD}
        float rx = Psx * cd + Psy * sd, ry2 = Psy * cd - Psx * sd; // Ps*e^{-iD}

        const float EPSF = 1e-14f;
        float nbn = fmaxf(sqrtf(osx * osx + osy * osy + 1e-30f), EPSF);
        float naL = fmaxf(sqrtf(lx * lx + ly * ly + 1e-30f), EPSF);
        float naR = fmaxf(sqrtf(rx * rx + ry2 * ry2 + 1e-30f), EPSF);
        float csL = (lx * osx + ly * osy) / (naL * nbn);
        float csR = (rx * osx + ry2 * osy) / (naR * nbn);
        bool left_closer = (csL >= csR);
        float bx = left_closer ? lx : rx;
        float by = left_closer ? ly : ry2;

        float d_abs = sqrtf(dax * dax + day * day);
        float ang;
        if (d_abs > 0.f) {
            ang = anglediff(dax, day, uix, uiy);
        } else {
            float babs = sqrtf(bx * bx + by * by);
            float bsx = (babs > 0.f) ? bx : 1.0f;
            float bsy = (babs > 0.f) ? by : 0.0f;
            ang = anglediff(bsx, bsy, uix, uiy);
        }

        const int io = g_sorig[s];
        const float C1   = (float)(0.2 * 25.0 * 0.0028);   // dt*Gamma*DR
        const float S2DR = (float)0.07483314773547883;     // sqrt(2*DR)
        const float SDT  = (float)0.4472135954999579;      // sqrt(dt)
        float phi = C1 * sinf(ang) + rnoise[io] * S2DR * SDT;
        float cr = cosf(phi), sr = sinf(phi);
        float nux = uix * cr - uiy * sr;
        float nuy = uix * sr + uiy * cr;

        const float DTV = (float)(0.2 * 5e-7);
        const float CSH = (float)0.7071067811865476;       // sqrt(0.5)
        const float C2T = (float)1.6733200530681511e-07;   // sqrt(2*DT_trans)
        float2 t = __ldg(&tn[io]);
        float tx = DTV * uix + ((t.x * CSH) * C2T) * SDT;
        float ty = DTV * uiy + ((t.y * CSH) * C2T) * SDT;

        if (lane == 0) {
            g_sposA[s] = make_float2(pix + tx, piy + ty);
            int b = 2 * n;
            out[1 * b + 2 * io + 0] = nux;  out[1 * b + 2 * io + 1] = nuy;
            out[2 * b + 2 * io + 0] = osx;  out[2 * b + 2 * io + 1] = osy;
            out[3 * b + 2 * io + 0] = lx;   out[3 * b + 2 * io + 1] = ly;
            out[4 * b + 2 * io + 0] = rx;   out[4 * b + 2 * io + 1] = ry2;
        }
    }
    grid_sync();

    // ---- P6-P8: three collision sweeps -------------------------------------------
    for (int s = gw; s < n; s += W) {
        float2 np = collide_one(g_sposA, s, lane);
        if (lane == 0) g_sposB[s] = np;
    }
    grid_sync();
    for (int s = gw; s < n; s += W) {
        float2 np = collide_one(g_sposB, s, lane);
        if (lane == 0) g_sposA[s] = np;
    }
    grid_sync();
    for (int s = gw; s < n; s += W) {
        float2 np = collide_one(g_sposA, s, lane);
        if (lane == 0) {
            int io = g_sorig[s];
            out[2 * io + 0] = np.x;
            out[2 * io + 1] = np.y;
        }
    }
}

extern "C" void kernel_launch(void* const* d_in, const int* in_sizes, int n_in,
                              void* d_out, int out_size) {
    const float* pos = (const float*)d_in[0];
    const float* ori = (const float*)d_in[1];
    const float* del = (const float*)d_in[2];
    const float* rno = (const float*)d_in[3];
    const float* tno = (const float*)d_in[4];
    float* out = (float*)d_out;
    const int n = in_sizes[3];                   // rot_noise has N elements

    fused_kernel<<<NB, TPB>>>((const float2*)pos, (const float2*)ori, del, rno,
                              (const float2*)tno, out, n);
}

// round 12
// speedup vs baseline: 1.2420x; 1.2420x over previous
#include <cuda_runtime.h>

// ActiveParticles step, N=4096 — spatial binning + ONE fused kernel,
// 1024 blocks x 128 threads (R7-proven co-resident shape), 7 grid barriers.
// Inputs: positions[N,2] f32, orientations[N,2] f32, Deltas[1] f32,
//         rot_noise[N] f32, trans_noise[N,2] f32.
// Output: [5, N, 2] f32 = {new_p, new_u, orientation_sums, leftturns, rightturns}.

#define NMAX  4096
#define GDIM  64
#define CELLS (GDIM * GDIM)

// Grid geometry: span [-2.24e-3, 2.24e-3], cell 7e-5 >= ROC (2.815e-5).
// Clamped cell mapping is monotone & non-expanding: any pair within ROC lands in
// adjacent cells, outliers included. Collision moves (~1e-5) << cell size, so the
// one-time binning stays valid for all 3 collision sweeps (radius 6.3e-6).
#define XMIN  (-2.24e-3f)
#define INVCS (14285.714285714286f)   // 1 / 7e-5

static __device__ float2   g_cms;
static __device__ float2   g_part[NMAX / 128];  // per-block mean partials
static __device__ float4   g_pu[NMAX];          // orig order (p.x,p.y,u.x,u.y)
static __device__ int      g_ci[NMAX];          // cell id per orig particle
static __device__ unsigned g_cnt[CELLS];        // ZERO-INVARIANT between runs
static __device__ unsigned g_start[CELLS + 1];
static __device__ unsigned g_cur[CELLS];
static __device__ float4   g_spu[NMAX];         // sorted (p,u)
static __device__ int      g_sorig[NMAX];       // sorted -> orig index
static __device__ int      g_scell[NMAX];       // sorted -> cell id
static __device__ float2   g_sposA[NMAX];       // sorted positions ping
static __device__ float2   g_sposB[NMAX];       // sorted positions pong
static __device__ volatile unsigned g_gen;      // barrier generation
static __device__ unsigned g_count;             // barrier arrivals

__device__ __forceinline__ float wsum(float v) {
#pragma unroll
    for (int o = 16; o; o >>= 1) v += __shfl_xor_sync(0xffffffffu, v, o);
    return v;
}

__device__ __forceinline__ unsigned uwscan(unsigned v, int lane) {  // inclusive
#pragma unroll
    for (int o = 1; o < 32; o <<= 1) {
        unsigned t = __shfl_up_sync(0xffffffffu, v, o);
        if (lane >= o) v += t;
    }
    return v;
}

__device__ __forceinline__ float anglewrap(float diff) {
    const float PI_F = 3.1415927410125732f;
    if (diff <= -PI_F) diff = diff - PI_F * floorf(diff / PI_F);  // jnp.mod(diff, PI)
    if (diff >= PI_F) diff -= 2.0f * PI_F;
    return diff;
}

__device__ __forceinline__ float anglediff(float ax, float ay, float bx, float by) {
    return anglewrap(atan2f(ay, ax) - atan2f(by, bx));
}

__device__ __forceinline__ int cell_of(float x, float y) {
    int cx = __float2int_rd((x - XMIN) * INVCS);
    int cy = __float2int_rd((y - XMIN) * INVCS);
    cx = max(0, min(GDIM - 1, cx));
    cy = max(0, min(GDIM - 1, cy));
    return cy * GDIM + cx;
}

// Grid barrier (R7-proven at 1024 blocks). __threadfence is gpu-scope ->
// post-barrier loads see other SMs' writes via coherent L2.
__device__ __forceinline__ void grid_sync(unsigned nb) {
    __syncthreads();
    if (threadIdx.x == 0) {
        unsigned my = g_gen;                     // read BEFORE arriving
        __threadfence();
        if (atomicAdd(&g_count, 1u) == nb - 1u) {
            g_count = 0u;
            __threadfence();
            g_gen = my + 1u;
        } else {
            while (g_gen == my) __nanosleep(40);
        }
        __threadfence();
    }
    __syncthreads();
}

// Load the 3x(row start,end) bounds with independent (predicated) loads: MLP 6.
__device__ __forceinline__ void row_bounds(int cx, int cy, int* A, int* B) {
    const int cx0 = max(cx - 1, 0), cx1 = min(cx + 1, GDIM - 1);
#pragma unroll
    for (int k = 0; k < 3; k++) {
        int ry = cy + k - 1;
        bool v = (unsigned)ry < (unsigned)GDIM;
        A[k] = v ? (int)g_start[ry * GDIM + cx0] : 0;
        B[k] = v ? (int)g_start[ry * GDIM + cx1 + 1] : 0;
    }
}

// One collision step for sorted slot s; result valid in all lanes.
__device__ __forceinline__ float2 collide_one(const float2* __restrict__ src,
                                              int s, int lane) {
    const float2 pi = src[s];
    const int c = g_scell[s];
    int A[3], B[3];
    row_bounds(c & (GDIM - 1), c >> 6, A, B);

    const float TH2 = (float)(2.0 * 3.15e-6) * (float)(2.0 * 3.15e-6);
    const float C21 = (float)(2.1 * 3.15e-6);
    const unsigned uTH2 = __float_as_uint(TH2);

    float mvx = 0.f, mvy = 0.f;
#pragma unroll
    for (int k = 0; k < 3; k++) {
        for (int idx = A[k] + lane; idx < B[k]; idx += 32) {
            float2 pj = src[idx];
            float dx = pj.x - pi.x, dyv = pj.y - pi.y;
            float d2 = fmaf(dx, dx, dyv * dyv);
            if ((__float_as_uint(d2) - 1u) < uTH2) {     // 0 < d2 <= TH2
                float ab = sqrtf(d2);
                float sc = (C21 - ab) * 0.5f / ab;
                mvx += dx * sc; mvy += dyv * sc;
            }
        }
    }
    mvx = wsum(mvx); mvy = wsum(mvy);
    return make_float2(pi.x - mvx, pi.y - mvy);
}

__global__ void __launch_bounds__(128, 8) fused_kernel(
        const float2* __restrict__ pos, const float2* __restrict__ ori,
        const float* __restrict__ deltas, const float* __restrict__ rnoise,
        const float2* __restrict__ tn, float* __restrict__ out,
        int n, unsigned nb) {
    const int tid  = threadIdx.x;
    const int bid  = blockIdx.x;
    const int lane = tid & 31;
    const int w    = tid >> 5;
    const int gtid = bid * 128 + tid;
    const int gw   = bid * 4 + w;               // global warp id == sorted slot

    __shared__ float2   s_red[4];
    __shared__ unsigned s_wt[4];

    // ---- P0: pack + count (g_cnt zero by invariant) + per-block mean partials ----
    {
        float px = 0.f, py = 0.f;
        if (gtid < n) {
            float2 pp = pos[gtid], uu = ori[gtid];
            g_pu[gtid] = make_float4(pp.x, pp.y, uu.x, uu.y);
            int c = cell_of(pp.x, pp.y);
            g_ci[gtid] = c;
            atomicAdd(&g_cnt[c], 1u);
            px = pp.x; py = pp.y;
        }
        px = wsum(px); py = wsum(py);
        if (bid * 128 < n) {
            if (lane == 0) s_red[w] = make_float2(px, py);
            __syncthreads();
            if (tid == 0)
                g_part[bid] = make_float2(s_red[0].x + s_red[1].x + s_red[2].x + s_red[3].x,
                                          s_red[0].y + s_red[1].y + s_red[2].y + s_red[3].y);
        }
    }
    grid_sync(nb);

    // ---- P1: block 0 scans counts -> g_start/g_cur; finishes mean ----------------
    if (bid == 0) {
        // thread t owns cells [32t, 32t+32)
        unsigned s = 0;
        for (int k = 0; k < 32; k++) s += g_cnt[32 * tid + k];
        unsigned inc = uwscan(s, lane);
        if (lane == 31) s_wt[w] = inc;
        __syncthreads();
        unsigned wbase = 0;
        for (int k = 0; k < w; k++) wbase += s_wt[k];
        unsigned base = wbase + inc - s;
        for (int k = 0; k < 32; k++) {
            unsigned c = g_cnt[32 * tid + k];
            g_start[32 * tid + k] = base;
            g_cur[32 * tid + k] = base;
            base += c;
        }
        if (tid == 127) g_start[CELLS] = base;   // == n
        if (w == 0) {
            float2 v = (lane * 128 < n) ? g_part[lane] : make_float2(0.f, 0.f);
            float ax = wsum(v.x), ay = wsum(v.y);
            if (lane == 0) {
                float invn = 1.0f / fmaxf((float)n, 1.0f);  // max(n_a,1), n_a=n
                g_cms = make_float2(ax * invn, ay * invn);
            }
        }
    }
    grid_sync(nb);

    // ---- P2: scatter (+ restore g_cnt zero-invariant) ----------------------------
    if (gtid < n) {
        int c = g_ci[gtid];
        unsigned slot = atomicAdd(&g_cur[c], 1u);
        g_spu[slot] = g_pu[gtid];
        g_sorig[slot] = gtid;
        g_scell[slot] = c;
    }
    if (gtid < CELLS) g_cnt[gtid] = 0u;
    grid_sync(nb);

    // ---- P3: per-cell insertion sort by orig index (determinism) -----------------
    if (gtid < CELLS) {
        int a = (int)g_start[gtid], b = (int)g_start[gtid + 1];
        for (int i = a + 1; i < b; i++) {
            float4 key = g_spu[i];
            int ko = g_sorig[i];
            int j = i - 1;
            while (j >= a && g_sorig[j] > ko) {
                g_spu[j + 1] = g_spu[j];
                g_sorig[j + 1] = g_sorig[j];
                j--;
            }
            g_spu[j + 1] = key;
            g_sorig[j + 1] = ko;
        }
    }
    grid_sync(nb);

    // ---- P4: main pass — warp per sorted slot ------------------------------------
    if (gw < n) {
        const int s = gw;
        const float4 me = g_spu[s];
        const float pix = me.x, piy = me.y, uix = me.z, uiy = me.w;
        const int c = g_scell[s];
        int A[3], B[3];
        row_bounds(c & (GDIM - 1), c >> 6, A, B);

        const float RR2  = (float)(8e-6 * 8e-6);
        const float ROCf = (float)(2.5e-5 + 3.15e-6);
        const float ROC2 = ROCf * ROCf;
        const unsigned uRR2 = __float_as_uint(RR2);

        float nr = 0.f, srx = 0.f, sry = 0.f, osx = 0.f, osy = 0.f;
#pragma unroll
        for (int k = 0; k < 3; k++) {
            for (int idx = A[k] + lane; idx < B[k]; idx += 32) {
                float4 aj = g_spu[idx];
                float dx = aj.x - pix, dyv = aj.y - piy;
                float d2 = fmaf(dx, dx, dyv * dyv);
                if (d2 <= ROC2) {                        // mask_ro (includes self)
                    osx += aj.z; osy += aj.w;
                    if ((__float_as_uint(d2) - 1u) < uRR2) {   // 0 < d2 <= RR2
                        // in_front: wrap(angle(dir)-angle(u_j)) < pi/2
                        //   <=> !(dot<=0 && cross>=0)
                        float cc2 = dx * aj.z + dyv * aj.w;
                        float ss2 = aj.z * dyv - aj.w * dx;
                        if (!(cc2 <= 0.0f && ss2 >= 0.0f)) { nr += 1.f; srx += aj.x; sry += aj.y; }
                    }
                }
            }
        }
        nr = wsum(nr); srx = wsum(srx); sry = wsum(sry); osx = wsum(osx); osy = wsum(osy);

        // epilogue (all lanes redundant, lane 0 writes)
        float sgn = (nr > 0.f) ? 1.0f : 0.0f;
        float invr = 1.0f / fmaxf(nr, 1.0f);
        float dax = -(srx * invr - pix * sgn);
        float day = -(sry * invr - piy * sgn);

        float2 cms = g_cms;
        float Psx = cms.x - pix;                         // sign(n_a) == 1
        float Psy = cms.y - piy;

        float Delta = __ldg(&deltas[0]);
        float cd = cosf(Delta), sd = sinf(Delta);
        float lx = Psx * cd - Psy * sd, ly = Psx * sd + Psy * cd;  // Ps*e^{+iD}
        float rx = Psx * cd + Psy * sd, ry2 = Psy * cd - Psx * sd; // Ps*e^{-iD}

        const float EPSF = 1e-14f;
        float nbn = fmaxf(sqrtf(osx * osx + osy * osy + 1e-30f), EPSF);
        float naL = fmaxf(sqrtf(lx * lx + ly * ly + 1e-30f), EPSF);
        float naR = fmaxf(sqrtf(rx * rx + ry2 * ry2 + 1e-30f), EPSF);
        float csL = (lx * osx + ly * osy) / (naL * nbn);
        float csR = (rx * osx + ry2 * osy) / (naR * nbn);
        bool left_closer = (csL >= csR);
        float bx = left_closer ? lx : rx;
        float by = left_closer ? ly : ry2;

        float d_abs = sqrtf(dax * dax + day * day);
        float ang;
        if (d_abs > 0.f) {
            ang = anglediff(dax, day, uix, uiy);
        } else {
            float babs = sqrtf(bx * bx + by * by);
            float bsx = (babs > 0.f) ? bx : 1.0f;
            float bsy = (babs > 0.f) ? by : 0.0f;
            ang = anglediff(bsx, bsy, uix, uiy);
        }

        const int io = g_sorig[s];
        const float C1   = (float)(0.2 * 25.0 * 0.0028);   // dt*Gamma*DR
        const float S2DR = (float)0.07483314773547883;     // sqrt(2*DR)
        const float SDT  = (float)0.4472135954999579;      // sqrt(dt)
        float phi = C1 * sinf(ang) + rnoise[io] * S2DR * SDT;
        float cr = cosf(phi), sr = sinf(phi);
        float nux = uix * cr - uiy * sr;
        float nuy = uix * sr + uiy * cr;

        const float DTV = (float)(0.2 * 5e-7);
        const float CSH = (float)0.7071067811865476;       // sqrt(0.5)
        const float C2T = (float)1.6733200530681511e-07;   // sqrt(2*DT_trans)
        float2 t = __ldg(&tn[io]);
        float tx = DTV * uix + ((t.x * CSH) * C2T) * SDT;
        float ty = DTV * uiy + ((t.y * CSH) * C2T) * SDT;

        if (lane == 0) {
            g_sposA[s] = make_float2(pix + tx, piy + ty);
            int b = 2 * n;
            out[1 * b + 2 * io + 0] = nux;  out[1 * b + 2 * io + 1] = nuy;
            out[2 * b + 2 * io + 0] = osx;  out[2 * b + 2 * io + 1] = osy;
            out[3 * b + 2 * io + 0] = lx;   out[3 * b + 2 * io + 1] = ly;
            out[4 * b + 2 * io + 0] = rx;   out[4 * b + 2 * io + 1] = ry2;
        }
    }
    grid_sync(nb);

    // ---- P5-P7: three collision sweeps -------------------------------------------
    if (gw < n) {
        float2 np = collide_one(g_sposA, gw, lane);
        if (lane == 0) g_sposB[gw] = np;
    }
    grid_sync(nb);
    if (gw < n) {
        float2 np = collide_one(g_sposB, gw, lane);
        if (lane == 0) g_sposA[gw] = np;
    }
    grid_sync(nb);
    if (gw < n) {
        float2 np = collide_one(g_sposA, gw, lane);
        if (lane == 0) {
            int io = g_sorig[gw];
            out[2 * io + 0] = np.x;
            out[2 * io + 1] = np.y;
        }
    }
}

extern "C" void kernel_launch(void* const* d_in, const int* in_sizes, int n_in,
                              void* d_out, int out_size) {
    const float* pos = (const float*)d_in[0];
    const float* ori = (const float*)d_in[1];
    const float* del = (const float*)d_in[2];
    const float* rno = (const float*)d_in[3];
    const float* tno = (const float*)d_in[4];
    float* out = (float*)d_out;
    const int n = in_sizes[3];                   // rot_noise has N elements

    const unsigned nb = (unsigned)((n + 3) / 4); // 1024 blocks (R7-proven co-resident)
    fused_kernel<<<nb, 128>>>((const float2*)pos, (const float2*)ori, del, rno,
                              (const float2*)tno, out, n, nb);
}

// round 13
// speedup vs baseline: 2.5779x; 2.0756x over previous
#include <cuda_runtime.h>

// ActiveParticles step, N=4096 — binned via fixed-capacity cell lists, 6 kernels,
// wide kernels packed as 128 CTAs x 1024 threads (4096 warps, minimal CTA dispatch).
// Inputs: positions[N,2] f32, orientations[N,2] f32, Deltas[1] f32,
//         rot_noise[N] f32, trans_noise[N,2] f32.
// Output: [5, N, 2] f32 = {new_p, new_u, orientation_sums, leftturns, rightturns}.

#define NMAX  4096
#define GDIM  64
#define CELLS (GDIM * GDIM)
#define CAP   64      // max particles/cell (center-cell Poisson mean ~12.8)

// Span [-2.24e-3, 2.24e-3], cell 7e-5 >= ROC (2.815e-5). Clamped mapping is
// monotone & non-expanding: any pair within ROC is in adjacent cells, outliers
// included. Collision moves (~1e-5) << cell size -> binning valid for all sweeps.
#define XMIN  (-2.24e-3f)
#define INVCS (14285.714285714286f)   // 1 / 7e-5

static __device__ float2   g_sum;              // atomic position sum (for cms)
static __device__ float4   g_pu[NMAX];         // (p.x,p.y,u.x,u.y) original order
static __device__ int      g_ci[NMAX];         // cell of particle i
static __device__ unsigned g_cellcnt[CELLS];
static __device__ int      g_celllist[CELLS * CAP];
static __device__ float2   g_posA[NMAX];       // positions ping (original order)
static __device__ float2   g_posB[NMAX];       // positions pong

__device__ __forceinline__ float wsum(float v) {
#pragma unroll
    for (int o = 16; o; o >>= 1) v += __shfl_xor_sync(0xffffffffu, v, o);
    return v;
}

__device__ __forceinline__ float anglewrap(float diff) {
    const float PI_F = 3.1415927410125732f;
    if (diff <= -PI_F) diff = diff - PI_F * floorf(diff / PI_F);  // jnp.mod(diff, PI)
    if (diff >= PI_F) diff -= 2.0f * PI_F;
    return diff;
}

__device__ __forceinline__ float anglediff(float ax, float ay, float bx, float by) {
    return anglewrap(atan2f(ay, ax) - atan2f(by, bx));
}

__device__ __forceinline__ int cell_of(float x, float y) {
    int cx = __float2int_rd((x - XMIN) * INVCS);
    int cy = __float2int_rd((y - XMIN) * INVCS);
    cx = max(0, min(GDIM - 1, cx));
    cy = max(0, min(GDIM - 1, cy));
    return cy * GDIM + cx;
}

// Load the 9 neighbor-cell ids + counts with independent loads.
__device__ __forceinline__ void nbr_cells(int c, int* cell9, int* cnt9) {
    const int cx = c & (GDIM - 1), cy = c >> 6;
#pragma unroll
    for (int ky = 0; ky < 3; ky++) {
#pragma unroll
        for (int kx = 0; kx < 3; kx++) {
            int rx = cx + kx - 1, ry = cy + ky - 1;
            bool v = ((unsigned)rx < (unsigned)GDIM) && ((unsigned)ry < (unsigned)GDIM);
            int cc = ry * GDIM + rx;
            cell9[ky * 3 + kx] = cc;
            cnt9[ky * 3 + kx] = v ? min((int)g_cellcnt[cc], CAP) : 0;
        }
    }
}

// ---- K0: zero counts + sum ---------------------------------------------------
__global__ void __launch_bounds__(1024) zero_kernel() {
    int t = blockIdx.x * blockDim.x + threadIdx.x;
    if (t < CELLS) g_cellcnt[t] = 0u;
    if (t == 0) g_sum = make_float2(0.f, 0.f);
}

// ---- K1: pack + bin into cell lists + mean atomics -----------------------------
__global__ void __launch_bounds__(1024) bin_kernel(const float2* __restrict__ p,
                                                   const float2* __restrict__ u, int n) {
    int i = blockIdx.x * blockDim.x + threadIdx.x;
    float px = 0.f, py = 0.f;
    if (i < n) {
        float2 pp = p[i], uu = u[i];
        g_pu[i] = make_float4(pp.x, pp.y, uu.x, uu.y);
        int c = cell_of(pp.x, pp.y);
        g_ci[i] = c;
        unsigned slot = atomicAdd(&g_cellcnt[c], 1u);
        g_celllist[c * CAP + min(slot, (unsigned)(CAP - 1))] = i;
        px = pp.x; py = pp.y;
    }
    px = wsum(px); py = wsum(py);
    if ((threadIdx.x & 31) == 0) {
        atomicAdd(&g_sum.x, px);
        atomicAdd(&g_sum.y, py);
    }
}

// ---- K2: main pass — warp per particle, 128 CTAs x 1024 thr ---------------------
__global__ void __launch_bounds__(1024) main_kernel(
        const float* __restrict__ deltas, const float* __restrict__ rnoise,
        const float2* __restrict__ tn, float* __restrict__ out, int n) {
    const int lane = threadIdx.x & 31;
    const int i = blockIdx.x * 32 + (threadIdx.x >> 5);   // particle (orig order)
    if (i >= n) return;

    const float4 me = g_pu[i];
    const float pix = me.x, piy = me.y, uix = me.z, uiy = me.w;

    int cell9[9], cnt9[9];
    nbr_cells(g_ci[i], cell9, cnt9);

    const float RR2  = (float)(8e-6 * 8e-6);
    const float ROCf = (float)(2.5e-5 + 3.15e-6);
    const float ROC2 = ROCf * ROCf;
    const unsigned uRR2 = __float_as_uint(RR2);

    float nr = 0.f, srx = 0.f, sry = 0.f, osx = 0.f, osy = 0.f;
#pragma unroll
    for (int k = 0; k < 9; k++) {
        const int base = cell9[k] * CAP;
        for (int t = lane; t < cnt9[k]; t += 32) {
            int j = g_celllist[base + t];
            float4 aj = g_pu[j];
            float dx = aj.x - pix, dyv = aj.y - piy;
            float d2 = fmaf(dx, dx, dyv * dyv);
            if (d2 <= ROC2) {                        // mask_ro (includes self)
                osx += aj.z; osy += aj.w;
                if ((__float_as_uint(d2) - 1u) < uRR2) {   // 0 < d2 <= RR2
                    // in_front: wrap(angle(dir)-angle(u_j)) < pi/2
                    //   <=> !(dot<=0 && cross>=0)
                    float cc = dx * aj.z + dyv * aj.w;
                    float ss = aj.z * dyv - aj.w * dx;
                    if (!(cc <= 0.0f && ss >= 0.0f)) { nr += 1.f; srx += aj.x; sry += aj.y; }
                }
            }
        }
    }
    nr = wsum(nr); srx = wsum(srx); sry = wsum(sry); osx = wsum(osx); osy = wsum(osy);

    // ---- epilogue (all lanes redundant, lane 0 writes) ----
    float sgn = (nr > 0.f) ? 1.0f : 0.0f;
    float invr = 1.0f / fmaxf(nr, 1.0f);
    float dax = -(srx * invr - pix * sgn);
    float day = -(sry * invr - piy * sgn);

    float2 sm = g_sum;
    float invn = 1.0f / fmaxf((float)n, 1.0f);       // max(n_a,1), n_a=n (mask_ra all-true)
    float Psx = sm.x * invn - pix;                   // sign(n_a)==1
    float Psy = sm.y * invn - piy;

    float Delta = __ldg(&deltas[0]);
    float cd = cosf(Delta), sd = sinf(Delta);
    float lx = Psx * cd - Psy * sd, ly = Psx * sd + Psy * cd;   // Ps*e^{+iD}
    float rx = Psx * cd + Psy * sd, ry = Psy * cd - Psx * sd;   // Ps*e^{-iD}

    const float EPSF = 1e-14f;
    float nbn = fmaxf(sqrtf(osx * osx + osy * osy + 1e-30f), EPSF);
    float naL = fmaxf(sqrtf(lx * lx + ly * ly + 1e-30f), EPSF);
    float naR = fmaxf(sqrtf(rx * rx + ry * ry + 1e-30f), EPSF);
    float csL = (lx * osx + ly * osy) / (naL * nbn);
    float csR = (rx * osx + ry * osy) / (naR * nbn);
    bool left_closer = (csL >= csR);
    float bx = left_closer ? lx : rx;
    float by = left_closer ? ly : ry;

    float d_abs = sqrtf(dax * dax + day * day);
    float ang;
    if (d_abs > 0.f) {
        ang = anglediff(dax, day, uix, uiy);
    } else {
        float babs = sqrtf(bx * bx + by * by);
        float bsx = (babs > 0.f) ? bx : 1.0f;
        float bsy = (babs > 0.f) ? by : 0.0f;
        ang = anglediff(bsx, bsy, uix, uiy);
    }

    const float C1   = (float)(0.2 * 25.0 * 0.0028);    // dt*Gamma*DR
    const float S2DR = (float)0.07483314773547883;      // sqrt(2*DR)
    const float SDT  = (float)0.4472135954999579;       // sqrt(dt)
    float phi = C1 * sinf(ang) + rnoise[i] * S2DR * SDT;
    float cr = cosf(phi), sr = sinf(phi);
    float nux = uix * cr - uiy * sr;
    float nuy = uix * sr + uiy * cr;

    const float DTV = (float)(0.2 * 5e-7);
    const float CSH = (float)0.7071067811865476;        // sqrt(0.5)
    const float C2T = (float)1.6733200530681511e-07;    // sqrt(2*DT_trans)
    float2 t = __ldg(&tn[i]);
    float tx = DTV * uix + ((t.x * CSH) * C2T) * SDT;
    float ty = DTV * uiy + ((t.y * CSH) * C2T) * SDT;

    if (lane == 0) {
        g_posA[i] = make_float2(pix + tx, piy + ty);
        int b = 2 * n;
        out[1 * b + 2 * i + 0] = nux;  out[1 * b + 2 * i + 1] = nuy;
        out[2 * b + 2 * i + 0] = osx;  out[2 * b + 2 * i + 1] = osy;
        out[3 * b + 2 * i + 0] = lx;   out[3 * b + 2 * i + 1] = ly;
        out[4 * b + 2 * i + 0] = rx;   out[4 * b + 2 * i + 1] = ry;
    }
}

// ---- K3-K5: collision sweep — warp per particle, 128 CTAs x 1024 thr -------------
// pass 0: A->B, 1: B->A, 2: A->out (row 0, original order).
__global__ void __launch_bounds__(1024) collide_kernel(int pass, float* __restrict__ out, int n) {
    const float2* __restrict__ src = (pass == 1) ? g_posB : g_posA;
    const int lane = threadIdx.x & 31;
    const int i = blockIdx.x * 32 + (threadIdx.x >> 5);
    if (i >= n) return;

    const float2 pi = src[i];
    int cell9[9], cnt9[9];
    nbr_cells(g_ci[i], cell9, cnt9);

    const float TH2 = (float)(2.0 * 3.15e-6) * (float)(2.0 * 3.15e-6);
    const float C21 = (float)(2.1 * 3.15e-6);
    const unsigned uTH2 = __float_as_uint(TH2);

    float mvx = 0.f, mvy = 0.f;
#pragma unroll
    for (int k = 0; k < 9; k++) {
        const int base = cell9[k] * CAP;
        for (int t = lane; t < cnt9[k]; t += 32) {
            int j = g_celllist[base + t];
            float2 pj = src[j];
            float dx = pj.x - pi.x, dyv = pj.y - pi.y;
            float d2 = fmaf(dx, dx, dyv * dyv);
            if ((__float_as_uint(d2) - 1u) < uTH2) {     // 0 < d2 <= TH2 (self excluded)
                float ab = sqrtf(d2);
                float sc = (C21 - ab) * 0.5f / ab;
                mvx += dx * sc; mvy += dyv * sc;
            }
        }
    }
    mvx = wsum(mvx); mvy = wsum(mvy);
    if (lane == 0) {
        float2 np = make_float2(pi.x - mvx, pi.y - mvy);
        if (pass == 0) g_posB[i] = np;
        else if (pass == 1) g_posA[i] = np;
        else { out[2 * i + 0] = np.x; out[2 * i + 1] = np.y; }
    }
}

extern "C" void kernel_launch(void* const* d_in, const int* in_sizes, int n_in,
                              void* d_out, int out_size) {
    const float* pos = (const float*)d_in[0];
    const float* ori = (const float*)d_in[1];
    const float* del = (const float*)d_in[2];
    const float* rno = (const float*)d_in[3];
    const float* tno = (const float*)d_in[4];
    float* out = (float*)d_out;
    const int n = in_sizes[3];                   // rot_noise has N elements

    const int wide = (n + 31) / 32;              // 128 CTAs of 1024 thr (warp/particle)

    zero_kernel<<<(CELLS + 1023) / 1024, 1024>>>();
    bin_kernel<<<(n + 1023) / 1024, 1024>>>((const float2*)pos, (const float2*)ori, n);
    main_kernel<<<wide, 1024>>>(del, rno, (const float2*)tno, out, n);
    collide_kernel<<<wide, 1024>>>(0, nullptr, n);
    collide_kernel<<<wide, 1024>>>(1, nullptr, n);
    collide_kernel<<<wide, 1024>>>(2, out, n);
}